// round 13
// baseline (speedup 1.0000x reference)
#include <cuda_runtime.h>
#include <math.h>

#define H 1024
#define W 1024
#define R 18
#define KS 37           // 2*R+1
#define NSTEP 16
#define W4 (W/4)
#define INV_N (1.0f/16.0f)
// fused blur tile
#define TW 128          // output tile width
#define TH 16           // output tile height
#define FC (TW + 40)    // staged cols: x0-20 .. x0+147 (need x0-18..x0+145)
#define FR (TH + 36)    // staged rows: y0-18 .. y0+33

// Persistent scratch (device globals: allowed; no runtime allocation)
__device__ float g_img[2][H*W];
__device__ float g_z[2][H*W];
__device__ float g_f[2][H*W];   // force: fx = -z*gx, fy = -z*gy
__device__ float g_v[2][H*W];   // velocity (vx, vy)

// ---------------------------------------------------------------------------
// Gaussian weights (sigma=6, radius 18), normalized; literals -> FFMA-imm.
__device__ __forceinline__ float wt(int i) {
    int d = i < R ? R - i : i - R;
    switch (d) {
        case 0:  return 0.066625152f;
        case 1:  return 0.065706198f;
        case 2:  return 0.063024692f;
        case 3:  return 0.058796492f;
        case 4:  return 0.053349252f;
        case 5:  return 0.047080544f;
        case 6:  return 0.040410194f;
        case 7:  return 0.033734705f;
        case 8:  return 0.027390419f;
        case 9:  return 0.021630020f;
        case 10: return 0.016613128f;
        case 11: return 0.012410281f;
        case 12: return 0.009016734f;
        case 13: return 0.006371659f;
        case 14: return 0.004379178f;
        case 15: return 0.002927305f;
        case 16: return 0.001903181f;
        case 17: return 0.001203452f;
        case 18: return 0.000740139f;
    }
    return 0.f;
}

__device__ __forceinline__ float get4(const float4& q, int e) {
    return e == 0 ? q.x : e == 1 ? q.y : e == 2 ? q.z : q.w;
}

// ---------------------------------------------------------------------------
// force: f = (-z*gx, -z*gy), central differences with replicate edges.
// One thread = 4 consecutive pixels (one float4).
__global__ __launch_bounds__(128) void force_k(const float* __restrict__ img,
                                               const float* __restrict__ z) {
    int c = blockIdx.x * blockDim.x + threadIdx.x;   // float4 column 0..255
    int y = blockIdx.y;
    int x0 = c * 4;
    int ym = max(y - 1, 0), yp = min(y + 1, H - 1);

    float4 ic = ((const float4*)(img + y  * W))[c];
    float4 iu = ((const float4*)(img + ym * W))[c];
    float4 id = ((const float4*)(img + yp * W))[c];
    float4 zz = ((const float4*)(z   + y  * W))[c];
    float left  = (x0 > 0)     ? img[y * W + x0 - 1] : ic.x;
    float right = (x0 + 4 < W) ? img[y * W + x0 + 4] : ic.w;

    float4 f0, f1;
    f0.x = -zz.x * 0.5f * (ic.y  - left);
    f0.y = -zz.y * 0.5f * (ic.z  - ic.x);
    f0.z = -zz.z * 0.5f * (ic.w  - ic.y);
    f0.w = -zz.w * 0.5f * (right - ic.z);
    f1.x = -zz.x * 0.5f * (id.x - iu.x);
    f1.y = -zz.y * 0.5f * (id.y - iu.y);
    f1.z = -zz.z * 0.5f * (id.z - iu.z);
    f1.w = -zz.w * 0.5f * (id.w - iu.w);

    ((float4*)g_f[0])[y * W4 + c] = f0;
    ((float4*)g_f[1])[y * W4 + c] = f1;
}

// ---------------------------------------------------------------------------
// Fused separable blur: g_f -> (vertical 37-tap) -> (horizontal 37-tap) -> g_v
// Block: 256 threads, output tile TW x TH per channel, channels sequential.
// Staged f patch covers all taps; replicate-clamped halo matches the
// reference's per-axis edge clamping exactly (t at a clamped col == t of the
// border col because the vertical blur is per-column).
__global__ __launch_bounds__(256) void blur_k() {
    __shared__ __align__(16) float sf[FR][FC];
    __shared__ __align__(16) float ts[TH][FC];

    int tid = threadIdx.x;
    int x0 = blockIdx.x * TW;
    int y0 = blockIdx.y * TH;

#pragma unroll 1
    for (int ch = 0; ch < 2; ch++) {
        const float* __restrict__ f = g_f[ch];

        // stage f patch (linear fill; clamped indices)
        for (int idx = tid; idx < FR * FC; idx += 256) {
            int r = idx / FC, c = idx % FC;
            int gy = min(max(y0 - 18 + r, 0), H - 1);
            int gx = min(max(x0 - 20 + c, 0), W - 1);
            sf[r][c] = f[gy * W + gx];
        }
        __syncthreads();

        // vertical pass: one column per thread (cols 0..FC-1), TH register acc
        if (tid < FC) {
            float acc[TH];
#pragma unroll
            for (int o = 0; o < TH; o++) acc[o] = 0.f;
#pragma unroll
            for (int j = 0; j < FR; j++) {          // staged row j = y0-18+j
                float v = sf[j][tid];
#pragma unroll
                for (int o = 0; o < TH; o++) {
                    int tap = j - o;                // (y0-18+j)-(y0+o-18)
                    if (tap >= 0 && tap < KS) acc[o] += wt(tap) * v;
                }
            }
#pragma unroll
            for (int o = 0; o < TH; o++) ts[o][tid] = acc[o];
        }
        __syncthreads();

        // horizontal pass: thread -> (row = tid/16, 8 consecutive out cols)
        {
            int row = tid >> 4;
            int xo  = (tid & 15) * 8;               // tile-local out col base
            float a[8];
#pragma unroll
            for (int o = 0; o < 8; o++) a[o] = 0.f;
            // need staged t cols xo+2 .. xo+45; read aligned xo+0 .. xo+47
            const float4* rp = (const float4*)&ts[row][xo];
#pragma unroll
            for (int c4 = 0; c4 < 12; c4++) {
                float4 q = rp[c4];
#pragma unroll
                for (int e = 0; e < 4; e++) {
                    int j = c4 * 4 + e;             // staged col xo + j
                    float v = get4(q, e);
#pragma unroll
                    for (int o = 0; o < 8; o++) {
                        int tap = j - 2 - o;        // (x0-20+xo+j)-(x0+xo+o-18)
                        if (tap >= 0 && tap < KS) a[o] += wt(tap) * v;
                    }
                }
            }
            float4* dst = (float4*)(g_v[ch] + (y0 + row) * W + x0 + xo);
            dst[0] = make_float4(a[0], a[1], a[2], a[3]);
            dst[1] = make_float4(a[4], a[5], a[6], a[7]);
        }
        __syncthreads();    // sf/ts reused by next channel
    }
}

// ---------------------------------------------------------------------------
// Bilinear sample of both fields with coordinate pre-clamping (== per-corner
// index clamping for mode='nearest', verified case-by-case).
__device__ __forceinline__ void bilin_zi(const float* __restrict__ z,
                                         const float* __restrict__ im,
                                         float cy, float cx,
                                         float& zr, float& ir) {
    cy = fminf(fmaxf(cy, 0.f), (float)(H - 1));
    cx = fminf(fmaxf(cx, 0.f), (float)(W - 1));
    float fy = floorf(cy), fx = floorf(cx);
    float wy = cy - fy,    wx = cx - fx;
    int y0 = (int)fy, x0 = (int)fx;
    int dx  = (x0 < W - 1) ? 1 : 0;
    int dyW = (y0 < H - 1) ? W : 0;
    int b   = y0 * W + x0;

    float z00 = z[b],        z01 = z[b + dx];
    float z10 = z[b + dyW],  z11 = z[b + dyW + dx];
    float i00 = im[b],       i01 = im[b + dx];
    float i10 = im[b + dyW], i11 = im[b + dyW + dx];

    float zt0 = z00 + wx * (z01 - z00);
    float zt1 = z10 + wx * (z11 - z10);
    zr = zt0 + wy * (zt1 - zt0);
    float it0 = i00 + wx * (i01 - i00);
    float it1 = i10 + wx * (i11 - i10);
    ir = it0 + wy * (it1 - it0);
}

// divergence + semi-Lagrangian update; 2 rows per thread (2 independent
// gather chains per thread for latency hiding; vy column shared).
__global__ __launch_bounds__(256) void advect_k(const float* __restrict__ zc,
                                                const float* __restrict__ ic,
                                                float* __restrict__ zout,
                                                float* __restrict__ iout) {
    int x   = blockIdx.x * blockDim.x + threadIdx.x;
    int y0r = blockIdx.y * 2;

    const float* __restrict__ vx = g_v[0];
    const float* __restrict__ vy = g_v[1];
    int xm = max(x - 1, 0), xp = min(x + 1, W - 1);
    int ya = max(y0r - 1, 0), yb = min(y0r + 2, H - 1);

    // vy column: rows y0r-1 .. y0r+2 (4 loads serve both rows)
    float vy_m = vy[ya * W + x];
    float vy_0 = vy[y0r * W + x];
    float vy_1 = vy[(y0r + 1) * W + x];
    float vy_p = vy[yb * W + x];

#pragma unroll
    for (int r = 0; r < 2; r++) {
        int y = y0r + r;
        int i = y * W + x;
        float vxc = vx[i];
        float vxm = vx[y * W + xm];
        float vxp = vx[y * W + xp];
        float vyc   = r ? vy_1 : vy_0;
        float vy_up = r ? vy_0 : vy_m;
        float vy_dn = r ? vy_p : vy_1;

        float div = 0.5f * (vxp - vxm) + 0.5f * (vy_dn - vy_up);

        float cy = (float)y - vyc * INV_N;
        float cx = (float)x - vxc * INV_N;

        float zw, iw;
        bilin_zi(zc, ic, cy, cx, zw, iw);

        float zold = zc[i];
        float znew = zw - zold * div * INV_N;
        float inew = iw + znew * INV_N;     // * MU / N, MU = 1

        zout[i] = znew;
        iout[i] = inew;
    }
}

// ---------------------------------------------------------------------------
extern "C" void kernel_launch(void* const* d_in, const int* in_sizes, int n_in,
                              void* d_out, int out_size) {
    const float* image = (const float*)d_in[0];
    const float* resid = (const float*)d_in[1];

    void* p_img = nullptr; void* p_z = nullptr;
    cudaGetSymbolAddress(&p_img, g_img);
    cudaGetSymbolAddress(&p_z, g_z);
    float* imgbuf[2] = {(float*)p_img, (float*)p_img + H * W};
    float* zbuf[2]   = {(float*)p_z,   (float*)p_z   + H * W};

    for (int s = 0; s < NSTEP; s++) {
        const float* ic = (s == 0) ? image : imgbuf[s & 1];
        const float* zc = (s == 0) ? resid : zbuf[s & 1];
        float* iout = (s == NSTEP - 1) ? (float*)d_out : imgbuf[(s + 1) & 1];
        float* zout = zbuf[(s + 1) & 1];

        force_k<<<dim3(W4 / 128, H), 128>>>(ic, zc);
        blur_k<<<dim3(W / TW, H / TH), 256>>>();
        advect_k<<<dim3(W / 256, H / 2), 256>>>(zc, ic, zout, iout);
    }
}

// round 15
// speedup vs baseline: 1.3929x; 1.3929x over previous
#include <cuda_runtime.h>
#include <math.h>

#define H 1024
#define W 1024
#define R 18
#define KS 37           // 2*R+1
#define NSTEP 16
#define VY 8            // output rows per thread in vertical blur
#define VX 8            // output cols per thread in horizontal blur
#define W4 (W/4)
#define INV_N (1.0f/16.0f)

// Persistent scratch (device globals: allowed; no runtime allocation)
__device__ float g_img[2][H*W];
__device__ float g_z[2][H*W];
__device__ float g_f[2][H*W];   // force: fx = -z*gx, fy = -z*gy
__device__ float g_t[2][H*W];   // after vertical blur
__device__ float g_v[2][H*W];   // velocity (vx, vy)

// ---------------------------------------------------------------------------
// Gaussian weights (sigma=6, radius 18), normalized; literals -> FFMA-imm.
__device__ __forceinline__ float wt(int i) {
    int d = i < R ? R - i : i - R;
    switch (d) {
        case 0:  return 0.066625152f;
        case 1:  return 0.065706198f;
        case 2:  return 0.063024692f;
        case 3:  return 0.058796492f;
        case 4:  return 0.053349252f;
        case 5:  return 0.047080544f;
        case 6:  return 0.040410194f;
        case 7:  return 0.033734705f;
        case 8:  return 0.027390419f;
        case 9:  return 0.021630020f;
        case 10: return 0.016613128f;
        case 11: return 0.012410281f;
        case 12: return 0.009016734f;
        case 13: return 0.006371659f;
        case 14: return 0.004379178f;
        case 15: return 0.002927305f;
        case 16: return 0.001903181f;
        case 17: return 0.001203452f;
        case 18: return 0.000740139f;
    }
    return 0.f;
}

__device__ __forceinline__ void fma4(float4& a, float w, const float4& v) {
    a.x += w * v.x; a.y += w * v.y; a.z += w * v.z; a.w += w * v.w;
}
__device__ __forceinline__ float get4(const float4& q, int e) {
    return e == 0 ? q.x : e == 1 ? q.y : e == 2 ? q.z : q.w;
}

// ---------------------------------------------------------------------------
// force: f = (-z*gx, -z*gy), central differences with replicate edges.
// One thread = 4 consecutive pixels x 2 rows (img row loads shared; 2
// independent chains per thread for latency hiding).
__global__ __launch_bounds__(128) void force_k(const float* __restrict__ img,
                                               const float* __restrict__ z) {
    int c  = blockIdx.x * blockDim.x + threadIdx.x;  // float4 column 0..255
    int y0 = blockIdx.y * 2;
    int x0 = c * 4;
    int ym = max(y0 - 1, 0);
    int yp = min(y0 + 2, H - 1);

    // img rows y0-1, y0, y0+1, y0+2 (shared by the 2 output rows)
    float4 r0 = ((const float4*)(img + ym        * W))[c];
    float4 r1 = ((const float4*)(img + y0        * W))[c];
    float4 r2 = ((const float4*)(img + (y0 + 1)  * W))[c];
    float4 r3 = ((const float4*)(img + yp        * W))[c];
    float4 z0 = ((const float4*)(z   + y0        * W))[c];
    float4 z1 = ((const float4*)(z   + (y0 + 1)  * W))[c];

    float l0  = (x0 > 0)     ? img[y0 * W + x0 - 1]       : r1.x;
    float rr0 = (x0 + 4 < W) ? img[y0 * W + x0 + 4]       : r1.w;
    float l1  = (x0 > 0)     ? img[(y0 + 1) * W + x0 - 1] : r2.x;
    float rr1 = (x0 + 4 < W) ? img[(y0 + 1) * W + x0 + 4] : r2.w;

    // row y0: gx from r1 neighbors, gy = 0.5*(r2 - r0)
    float4 f0a, f1a;
    f0a.x = -z0.x * 0.5f * (r1.y - l0);
    f0a.y = -z0.y * 0.5f * (r1.z - r1.x);
    f0a.z = -z0.z * 0.5f * (r1.w - r1.y);
    f0a.w = -z0.w * 0.5f * (rr0  - r1.z);
    f1a.x = -z0.x * 0.5f * (r2.x - r0.x);
    f1a.y = -z0.y * 0.5f * (r2.y - r0.y);
    f1a.z = -z0.z * 0.5f * (r2.z - r0.z);
    f1a.w = -z0.w * 0.5f * (r2.w - r0.w);

    // row y0+1: gx from r2 neighbors, gy = 0.5*(r3 - r1)
    float4 f0b, f1b;
    f0b.x = -z1.x * 0.5f * (r2.y - l1);
    f0b.y = -z1.y * 0.5f * (r2.z - r2.x);
    f0b.z = -z1.z * 0.5f * (r2.w - r2.y);
    f0b.w = -z1.w * 0.5f * (rr1  - r2.z);
    f1b.x = -z1.x * 0.5f * (r3.x - r1.x);
    f1b.y = -z1.y * 0.5f * (r3.y - r1.y);
    f1b.z = -z1.z * 0.5f * (r3.z - r1.z);
    f1b.w = -z1.w * 0.5f * (r3.w - r1.w);

    ((float4*)g_f[0])[y0 * W4 + c]       = f0a;
    ((float4*)g_f[1])[y0 * W4 + c]       = f1a;
    ((float4*)g_f[0])[(y0 + 1) * W4 + c] = f0b;
    ((float4*)g_f[1])[(y0 + 1) * W4 + c] = f1b;
}

// ---------------------------------------------------------------------------
// vertical blur: one thread = one float4 column x VY rows x 2 channels
__global__ __launch_bounds__(64, 4) void vblur_k() {
    int c  = blockIdx.x * blockDim.x + threadIdx.x;  // float4 column 0..255
    int y0 = blockIdx.y * VY;

    const float4* __restrict__ f0p = (const float4*)g_f[0];
    const float4* __restrict__ f1p = (const float4*)g_f[1];

    float4 a0[VY], a1[VY];
#pragma unroll
    for (int o = 0; o < VY; o++) {
        a0[o] = make_float4(0.f, 0.f, 0.f, 0.f);
        a1[o] = make_float4(0.f, 0.f, 0.f, 0.f);
    }

#pragma unroll
    for (int j = 0; j < KS + VY - 1; j++) {      // input rows y0-R+j
        int yy = y0 - R + j;
        yy = max(0, min(H - 1, yy));
        float4 f0 = f0p[yy * W4 + c];
        float4 f1 = f1p[yy * W4 + c];
#pragma unroll
        for (int o = 0; o < VY; o++) {
            int tap = j - o;
            if (tap >= 0 && tap < KS) {
                float w = wt(tap);
                fma4(a0[o], w, f0);
                fma4(a1[o], w, f1);
            }
        }
    }
#pragma unroll
    for (int o = 0; o < VY; o++) {
        ((float4*)g_t[0])[(y0 + o) * W4 + c] = a0[o];
        ((float4*)g_t[1])[(y0 + o) * W4 + c] = a1[o];
    }
}

// ---------------------------------------------------------------------------
// horizontal blur: one thread = VX=8 consecutive cols, channels sequential.
// 64-thread blocks, 2 blocks per row (better SM balance / latency hiding).
__global__ __launch_bounds__(64) void hblur_k() {
    int tc = blockIdx.y * 64 + threadIdx.x;   // global column-group 0..127
    int y  = blockIdx.x;                      // one row
    int x0 = tc * VX;

    bool interior = (tc >= 3 && tc <= 124);

#pragma unroll
    for (int ch = 0; ch < 2; ch++) {
        const float* __restrict__ row = g_t[ch] + y * W;
        float a[VX];
#pragma unroll
        for (int o = 0; o < VX; o++) a[o] = 0.f;

        if (interior) {
            // inputs needed: [x0-18, x0+25]; aligned window [x0-20, x0+28)
            const float4* r = (const float4*)(row + x0 - 20);
#pragma unroll
            for (int c4 = 0; c4 < 12; c4++) {
                float4 q = r[c4];
#pragma unroll
                for (int e = 0; e < 4; e++) {
                    int j = c4 * 4 + e;            // input x = x0-20+j
                    float v = get4(q, e);
#pragma unroll
                    for (int o = 0; o < VX; o++) {
                        int tap = j - 2 - o;        // (x0-20+j) - (x0+o-18)
                        if (tap >= 0 && tap < KS) a[o] += wt(tap) * v;
                    }
                }
            }
        } else {
#pragma unroll
            for (int j = 0; j < KS + VX - 1; j++) { // input x = x0-R+j
                int xx = x0 - R + j;
                xx = max(0, min(W - 1, xx));
                float v = row[xx];
#pragma unroll
                for (int o = 0; o < VX; o++) {
                    int tap = j - o;
                    if (tap >= 0 && tap < KS) a[o] += wt(tap) * v;
                }
            }
        }
        // v = smooth * (RHO/MU), RHO=MU=1
        float4* dst = (float4*)(g_v[ch] + y * W + x0);
        dst[0] = make_float4(a[0], a[1], a[2], a[3]);
        dst[1] = make_float4(a[4], a[5], a[6], a[7]);
    }
}

// ---------------------------------------------------------------------------
// Bilinear sample of both fields with coordinate pre-clamping (== per-corner
// index clamping for mode='nearest', verified case-by-case).
__device__ __forceinline__ void bilin_zi(const float* __restrict__ z,
                                         const float* __restrict__ im,
                                         float cy, float cx,
                                         float& zr, float& ir) {
    cy = fminf(fmaxf(cy, 0.f), (float)(H - 1));
    cx = fminf(fmaxf(cx, 0.f), (float)(W - 1));
    float fy = floorf(cy), fx = floorf(cx);
    float wy = cy - fy,    wx = cx - fx;
    int y0 = (int)fy, x0 = (int)fx;
    int dx  = (x0 < W - 1) ? 1 : 0;
    int dyW = (y0 < H - 1) ? W : 0;
    int b   = y0 * W + x0;

    float z00 = z[b],        z01 = z[b + dx];
    float z10 = z[b + dyW],  z11 = z[b + dyW + dx];
    float i00 = im[b],       i01 = im[b + dx];
    float i10 = im[b + dyW], i11 = im[b + dyW + dx];

    float zt0 = z00 + wx * (z01 - z00);
    float zt1 = z10 + wx * (z11 - z10);
    zr = zt0 + wy * (zt1 - zt0);
    float it0 = i00 + wx * (i01 - i00);
    float it1 = i10 + wx * (i11 - i10);
    ir = it0 + wy * (it1 - it0);
}

// divergence + semi-Lagrangian update; 2 rows per thread (2 independent
// gather chains per thread for latency hiding; vy column shared).
__global__ __launch_bounds__(256) void advect_k(const float* __restrict__ zc,
                                                const float* __restrict__ ic,
                                                float* __restrict__ zout,
                                                float* __restrict__ iout) {
    int x   = blockIdx.x * blockDim.x + threadIdx.x;
    int y0r = blockIdx.y * 2;

    const float* __restrict__ vx = g_v[0];
    const float* __restrict__ vy = g_v[1];
    int xm = max(x - 1, 0), xp = min(x + 1, W - 1);
    int ya = max(y0r - 1, 0), yb = min(y0r + 2, H - 1);

    // vy column: rows y0r-1 .. y0r+2 (4 loads serve both rows)
    float vy_m = vy[ya * W + x];
    float vy_0 = vy[y0r * W + x];
    float vy_1 = vy[(y0r + 1) * W + x];
    float vy_p = vy[yb * W + x];

#pragma unroll
    for (int r = 0; r < 2; r++) {
        int y = y0r + r;
        int i = y * W + x;
        float vxc = vx[i];
        float vxm = vx[y * W + xm];
        float vxp = vx[y * W + xp];
        float vyc   = r ? vy_1 : vy_0;
        float vy_up = r ? vy_0 : vy_m;
        float vy_dn = r ? vy_p : vy_1;

        float div = 0.5f * (vxp - vxm) + 0.5f * (vy_dn - vy_up);

        float cy = (float)y - vyc * INV_N;
        float cx = (float)x - vxc * INV_N;

        float zw, iw;
        bilin_zi(zc, ic, cy, cx, zw, iw);

        float zold = zc[i];
        float znew = zw - zold * div * INV_N;
        float inew = iw + znew * INV_N;     // * MU / N, MU = 1

        zout[i] = znew;
        iout[i] = inew;
    }
}

// ---------------------------------------------------------------------------
extern "C" void kernel_launch(void* const* d_in, const int* in_sizes, int n_in,
                              void* d_out, int out_size) {
    const float* image = (const float*)d_in[0];
    const float* resid = (const float*)d_in[1];

    void* p_img = nullptr; void* p_z = nullptr;
    cudaGetSymbolAddress(&p_img, g_img);
    cudaGetSymbolAddress(&p_z, g_z);
    float* imgbuf[2] = {(float*)p_img, (float*)p_img + H * W};
    float* zbuf[2]   = {(float*)p_z,   (float*)p_z   + H * W};

    for (int s = 0; s < NSTEP; s++) {
        const float* ic = (s == 0) ? image : imgbuf[s & 1];
        const float* zc = (s == 0) ? resid : zbuf[s & 1];
        float* iout = (s == NSTEP - 1) ? (float*)d_out : imgbuf[(s + 1) & 1];
        float* zout = zbuf[(s + 1) & 1];

        force_k<<<dim3(W4 / 128, H / 2), 128>>>(ic, zc);
        vblur_k<<<dim3(W4 / 64, H / VY), 64>>>();
        hblur_k<<<dim3(H, 2), 64>>>();
        advect_k<<<dim3(W / 256, H / 2), 256>>>(zc, ic, zout, iout);
    }
}